// round 1
// baseline (speedup 1.0000x reference)
#include <cuda_runtime.h>

#define V  32000
#define SQ 256
#define BQ 16
#define HQ 16

// scratch (allocation-free rule: __device__ globals)
__device__ float g_xproj[2 * SQ * BQ * HQ];        // [dir][s][b][h]
__device__ float g_hcat[SQ * BQ * 2 * HQ];         // [s][b][32]

__device__ __forceinline__ unsigned long long pack2(float lo, float hi) {
    unsigned long long r;
    asm("mov.b64 %0, {%1,%2};" : "=l"(r) : "f"(lo), "f"(hi));
    return r;
}
__device__ __forceinline__ void fma2(unsigned long long &d, unsigned long long a, unsigned long long b) {
    asm("fma.rn.f32x2 %0, %1, %2, %0;" : "+l"(d) : "l"(a), "l"(b));
}
__device__ __forceinline__ float2 unpack2(unsigned long long v) {
    float2 r;
    asm("mov.b64 {%0,%1}, %2;" : "=f"(r.x), "=f"(r.y) : "l"(v));
    return r;
}

// ---------------------------------------------------------------------------
// Kernel A: xproj[dir][s][b][h] = emb[tok[s,b]] . W_ih[0:32, h] + b_ih[h]
// ---------------------------------------------------------------------------
__global__ void xproj_kernel(const int* __restrict__ tok,
                             const float* __restrict__ emb,
                             const float* __restrict__ W_lr, const float* __restrict__ b_lr,
                             const float* __restrict__ W_rl, const float* __restrict__ b_rl) {
    int idx = blockIdx.x * blockDim.x + threadIdx.x;
    if (idx >= 2 * SQ * BQ * HQ) return;
    int h   = idx & 15;
    int b   = (idx >> 4) & 15;
    int s   = (idx >> 8) & 255;
    int dir = idx >> 16;
    const float* W  = dir ? W_rl : W_lr;
    const float* bb = dir ? b_rl : b_lr;
    int t = tok[s * BQ + b];
    float acc = bb[h];
    const float* erow = emb + (size_t)t * 32;
#pragma unroll
    for (int e = 0; e < 32; e++)
        acc = fmaf(erow[e], W[e * HQ + h], acc);
    g_xproj[idx] = acc;
}

// ---------------------------------------------------------------------------
// Kernel B: sequential RNN scans. 16 blocks (one per batch b) x 32 threads.
// Lanes 0-15: left-to-right (h = lane).  Lanes 16-31: right-to-left (h = lane&15).
// Warp-synchronous; no barriers. Writes hcat directly at the "used" positions.
// ---------------------------------------------------------------------------
__global__ void rnn_kernel(const float* __restrict__ mask_lr,
                           const float* __restrict__ mask_rl,
                           const float* __restrict__ W_lr,
                           const float* __restrict__ W_rl,
                           const float* __restrict__ h0p) {
    const int b    = blockIdx.x;
    const int lane = threadIdx.x;
    const bool rl  = lane >= 16;
    const int h    = lane & 15;
    const unsigned grpbase = lane & 16;

    const float* W    = rl ? W_rl : W_lr;
    const float* mask = rl ? mask_rl : mask_lr;
    const float* xp   = g_xproj + (rl ? SQ * BQ * HQ : 0);

    float Wh[16];
#pragma unroll
    for (int j = 0; j < 16; j++)
        Wh[j] = W[(32 + j) * HQ + h];   // recurrent block rows of W_ih

    float hv = h0p[h];
    // boundary entries of hcat
    if (!rl) g_hcat[(0 * BQ + b) * 32 + h]              = hv;
    else     g_hcat[((SQ - 1) * BQ + b) * 32 + 16 + h]  = hv;

    for (int t = 0; t < SQ; t++) {
        int s = rl ? (SQ - 1 - t) : t;
        float acc = xp[(s * BQ + b) * HQ + h];
        float m   = mask[(s * BQ + b) * HQ + h];
#pragma unroll
        for (int j = 0; j < 16; j++) {
            float hj = __shfl_sync(0xffffffffu, hv, grpbase + j);
            acc = fmaf(Wh[j], hj, acc);
        }
        hv = tanhf(acc) * (m * (1.0f / 0.6f));
        if (!rl) {
            if (s < SQ - 1) g_hcat[((s + 1) * BQ + b) * 32 + h] = hv;
        } else {
            if (s > 0)      g_hcat[((s - 1) * BQ + b) * 32 + 16 + h] = hv;
        }
    }
}

// ---------------------------------------------------------------------------
// Kernel C: logits = hcat @ W_ho + b_ho; out = log_softmax over V.
// 256 CTAs x 16 rows. Pass 1: lse via fixed-shift (C=16) sum-exp (no max pass).
// Pass 2: recompute logits, subtract lse, streaming-store output.
// Inner product uses packed f32x2 FMA; A held in smem pre-duplicated {a,a}.
// ---------------------------------------------------------------------------
__global__ void __launch_bounds__(256, 2)
logits_kernel(const float* __restrict__ W, const float* __restrict__ bho,
              float* __restrict__ out) {
    __shared__ __align__(16) unsigned long long As2[32][16];  // [feature h][row m] = {a,a}
    __shared__ float s_lse[16];
    __shared__ float s_red[8][16];

    const int tid = threadIdx.x;
    const int m0  = blockIdx.x * 16;

    for (int i = tid; i < 16 * 32; i += 256) {
        int m = i >> 5, f = i & 31;
        float a = g_hcat[(m0 + m) * 32 + f];
        As2[f][m] = pack2(a, a);
    }
    __syncthreads();

    float sums[16];
#pragma unroll
    for (int m = 0; m < 16; m++) sums[m] = 0.f;

    // ---------------- Pass 1: accumulate sum(exp(logit - 16)) per row -------
    for (int v0 = tid * 4; v0 < V; v0 += 1024) {
        const float4 bh = *reinterpret_cast<const float4*>(bho + v0);
#pragma unroll
        for (int half = 0; half < 2; half++) {
            unsigned long long acc0[8], acc1[8];
            unsigned long long i01 = pack2(bh.x - 16.f, bh.y - 16.f);
            unsigned long long i23 = pack2(bh.z - 16.f, bh.w - 16.f);
#pragma unroll
            for (int mi = 0; mi < 8; mi++) { acc0[mi] = i01; acc1[mi] = i23; }
#pragma unroll 8
            for (int hh = 0; hh < 32; hh++) {
                ulonglong2 w = *reinterpret_cast<const ulonglong2*>(W + hh * V + v0);
                const ulonglong2* ap = reinterpret_cast<const ulonglong2*>(&As2[hh][half * 8]);
                ulonglong2 a01 = ap[0], a23 = ap[1], a45 = ap[2], a67 = ap[3];
                unsigned long long av[8] = {a01.x, a01.y, a23.x, a23.y, a45.x, a45.y, a67.x, a67.y};
#pragma unroll
                for (int mi = 0; mi < 8; mi++) {
                    fma2(acc0[mi], av[mi], w.x);
                    fma2(acc1[mi], av[mi], w.y);
                }
            }
#pragma unroll
            for (int mi = 0; mi < 8; mi++) {
                float2 p0 = unpack2(acc0[mi]);
                float2 p1 = unpack2(acc1[mi]);
                sums[half * 8 + mi] +=
                    (__expf(p0.x) + __expf(p0.y)) + (__expf(p1.x) + __expf(p1.y));
            }
        }
    }

    // ---------------- Block reduction -> lse per row ------------------------
    const int lane = tid & 31, wid = tid >> 5;
#pragma unroll
    for (int m = 0; m < 16; m++) {
        float v = sums[m];
        v += __shfl_xor_sync(0xffffffffu, v, 16);
        v += __shfl_xor_sync(0xffffffffu, v, 8);
        v += __shfl_xor_sync(0xffffffffu, v, 4);
        v += __shfl_xor_sync(0xffffffffu, v, 2);
        v += __shfl_xor_sync(0xffffffffu, v, 1);
        if (lane == 0) s_red[wid][m] = v;
    }
    __syncthreads();
    if (tid < 16) {
        float t = 0.f;
#pragma unroll
        for (int w = 0; w < 8; w++) t += s_red[w][tid];
        s_lse[tid] = 16.f + logf(t);
    }
    __syncthreads();

    // ---------------- Pass 2: recompute, normalize, store -------------------
    for (int v0 = tid * 4; v0 < V; v0 += 1024) {
        const float4 bh = *reinterpret_cast<const float4*>(bho + v0);
#pragma unroll
        for (int half = 0; half < 2; half++) {
            unsigned long long acc0[8], acc1[8];
            unsigned long long i01 = pack2(bh.x, bh.y);
            unsigned long long i23 = pack2(bh.z, bh.w);
#pragma unroll
            for (int mi = 0; mi < 8; mi++) { acc0[mi] = i01; acc1[mi] = i23; }
#pragma unroll 8
            for (int hh = 0; hh < 32; hh++) {
                ulonglong2 w = *reinterpret_cast<const ulonglong2*>(W + hh * V + v0);
                const ulonglong2* ap = reinterpret_cast<const ulonglong2*>(&As2[hh][half * 8]);
                ulonglong2 a01 = ap[0], a23 = ap[1], a45 = ap[2], a67 = ap[3];
                unsigned long long av[8] = {a01.x, a01.y, a23.x, a23.y, a45.x, a45.y, a67.x, a67.y};
#pragma unroll
                for (int mi = 0; mi < 8; mi++) {
                    fma2(acc0[mi], av[mi], w.x);
                    fma2(acc1[mi], av[mi], w.y);
                }
            }
#pragma unroll
            for (int mi = 0; mi < 8; mi++) {
                int m = half * 8 + mi;
                float lse = s_lse[m];
                float2 p0 = unpack2(acc0[mi]);
                float2 p1 = unpack2(acc1[mi]);
                float4 o = make_float4(p0.x - lse, p0.y - lse, p1.x - lse, p1.y - lse);
                __stcs(reinterpret_cast<float4*>(out + (size_t)(m0 + m) * V + v0), o);
            }
        }
    }
}

// ---------------------------------------------------------------------------
extern "C" void kernel_launch(void* const* d_in, const int* in_sizes, int n_in,
                              void* d_out, int out_size) {
    const int*   tok     = (const int*)  d_in[0];
    const float* mask_lr = (const float*)d_in[1];
    const float* mask_rl = (const float*)d_in[2];
    const float* emb     = (const float*)d_in[3];
    const float* W_lr    = (const float*)d_in[4];
    const float* b_lr    = (const float*)d_in[5];
    const float* W_rl    = (const float*)d_in[6];
    const float* b_rl    = (const float*)d_in[7];
    const float* W_ho    = (const float*)d_in[8];
    const float* b_ho    = (const float*)d_in[9];
    const float* h0      = (const float*)d_in[10];
    float* out = (float*)d_out;

    xproj_kernel<<<512, 256>>>(tok, emb, W_lr, b_lr, W_rl, b_rl);
    rnn_kernel<<<16, 32>>>(mask_lr, mask_rl, W_lr, W_rl, h0);
    logits_kernel<<<256, 256>>>(W_ho, b_ho, out);
}

// round 3
// speedup vs baseline: 1.3177x; 1.3177x over previous
#include <cuda_runtime.h>
#include <cuda_bf16.h>
#include <cstdint>

#define V  32000
#define SQ 256
#define BQ 16
#define HQ 16
#define MT 4096            // rows = SQ*BQ
#define NB 250             // N blocks (32000/128)
#define KD 96              // split-K depth: [hi|hi|lo] x [hi|lo|hi]

// ---------------- scratch (__device__ globals; no allocs) -------------------
__device__ float g_xproj[2 * SQ * BQ * HQ];
__device__ float g_hcat[MT * 32];
__device__ __nv_bfloat16 g_Abf[MT * KD];
__device__ __nv_bfloat16 g_Bbf[(size_t)V * KD];
__device__ float g_part[(size_t)NB * MT];
__device__ float g_lse[MT];

__device__ __forceinline__ uint32_t smem_u32(const void* p) {
    uint32_t a;
    asm("{ .reg .u64 t; cvta.to.shared.u64 t, %1; cvt.u32.u64 %0, t; }" : "=r"(a) : "l"(p));
    return a;
}
__device__ __forceinline__ void ldsm_x2(uint32_t& r0, uint32_t& r1, uint32_t addr) {
    asm volatile("ldmatrix.sync.aligned.m8n8.x2.shared.b16 {%0,%1}, [%2];"
                 : "=r"(r0), "=r"(r1) : "r"(addr));
}
__device__ __forceinline__ void mma16816(float* c, const uint32_t* a, uint32_t b0, uint32_t b1) {
    asm volatile("mma.sync.aligned.m16n8k16.row.col.f32.bf16.bf16.f32 "
                 "{%0,%1,%2,%3}, {%4,%5,%6,%7}, {%8,%9}, {%0,%1,%2,%3};"
                 : "+f"(c[0]), "+f"(c[1]), "+f"(c[2]), "+f"(c[3])
                 : "r"(a[0]), "r"(a[1]), "r"(a[2]), "r"(a[3]), "r"(b0), "r"(b1));
}
__device__ __forceinline__ void stcs2(float* p, float x, float y) {
    asm volatile("st.global.cs.v2.f32 [%0], {%1,%2};" :: "l"(p), "f"(x), "f"(y) : "memory");
}

// ---------------------------------------------------------------------------
__global__ void xproj_kernel(const int* __restrict__ tok, const float* __restrict__ emb,
                             const float* __restrict__ W_lr, const float* __restrict__ b_lr,
                             const float* __restrict__ W_rl, const float* __restrict__ b_rl) {
    int idx = blockIdx.x * blockDim.x + threadIdx.x;
    if (idx >= 2 * SQ * BQ * HQ) return;
    int h = idx & 15, b = (idx >> 4) & 15, s = (idx >> 8) & 255, dir = idx >> 16;
    const float* W = dir ? W_rl : W_lr;
    const float* bb = dir ? b_rl : b_lr;
    int t = tok[s * BQ + b];
    float acc = bb[h];
    const float* erow = emb + (size_t)t * 32;
#pragma unroll
    for (int e = 0; e < 32; e++) acc = fmaf(erow[e], W[e * HQ + h], acc);
    g_xproj[idx] = acc;
}

__global__ void rnn_kernel(const float* __restrict__ mask_lr, const float* __restrict__ mask_rl,
                           const float* __restrict__ W_lr, const float* __restrict__ W_rl,
                           const float* __restrict__ h0p) {
    const int b = blockIdx.x, lane = threadIdx.x;
    const bool rl = lane >= 16;
    const int h = lane & 15;
    const unsigned grpbase = lane & 16;
    const float* W = rl ? W_rl : W_lr;
    const float* mask = rl ? mask_rl : mask_lr;
    const float* xp = g_xproj + (rl ? SQ * BQ * HQ : 0);
    float Wh[16];
#pragma unroll
    for (int j = 0; j < 16; j++) Wh[j] = W[(32 + j) * HQ + h];
    float hv = h0p[h];
    if (!rl) g_hcat[(0 * BQ + b) * 32 + h] = hv;
    else     g_hcat[((SQ - 1) * BQ + b) * 32 + 16 + h] = hv;
    for (int t = 0; t < SQ; t++) {
        int s = rl ? (SQ - 1 - t) : t;
        float acc = xp[(s * BQ + b) * HQ + h];
        float m = mask[(s * BQ + b) * HQ + h];
#pragma unroll
        for (int j = 0; j < 16; j++) {
            float hj = __shfl_sync(0xffffffffu, hv, grpbase + j);
            acc = fmaf(Wh[j], hj, acc);
        }
        hv = tanhf(acc) * (m * (1.0f / 0.6f));
        if (!rl) { if (s < SQ - 1) g_hcat[((s + 1) * BQ + b) * 32 + h] = hv; }
        else     { if (s > 0)      g_hcat[((s - 1) * BQ + b) * 32 + 16 + h] = hv; }
    }
}

// A row m: [hi(32) | hi(32) | lo(32)]
__global__ void prepA_kernel() {
    int idx = blockIdx.x * blockDim.x + threadIdx.x;
    if (idx >= MT * 32) return;
    int m = idx >> 5, f = idx & 31;
    float a = g_hcat[m * 32 + f];
    __nv_bfloat16 hi = __float2bfloat16(a);
    __nv_bfloat16 lo = __float2bfloat16(a - __bfloat162float(hi));
    __nv_bfloat16* r = g_Abf + m * KD;
    r[f] = hi; r[32 + f] = hi; r[64 + f] = lo;
}

// B row n: [hi(32) | lo(32) | hi(32)],  w[k] = W_ho[k][n]
__global__ void prepB_kernel(const float* __restrict__ Who) {
    int idx = blockIdx.x * blockDim.x + threadIdx.x;
    if (idx >= V * 32) return;
    int n = idx >> 5, k = idx & 31;
    float w = Who[k * V + n];
    __nv_bfloat16 hi = __float2bfloat16(w);
    __nv_bfloat16 lo = __float2bfloat16(w - __bfloat162float(hi));
    __nv_bfloat16* r = g_Bbf + (size_t)n * KD;
    r[k] = hi; r[32 + k] = lo; r[64 + k] = hi;
}

// ---------------------------------------------------------------------------
// GEMM via mma.sync m16n8k16 bf16. CTA 128x128, warps 4(M) x 2(N), warp 32x64.
// PASS 1: lse partials. PASS 2: normalize + streaming store.
// ---------------------------------------------------------------------------
template <int PASS>
__global__ void __launch_bounds__(256, 2)
gemm_kernel(const float* __restrict__ bho, float* __restrict__ out) {
    __shared__ __align__(16) __nv_bfloat16 Bs[128 * 104];   // pad to 104 (stride 13x16B)
    __shared__ float s_bias[128];
    __shared__ float s_red[256];

    const int tid = threadIdx.x, w = tid >> 5, l = tid & 31;
    const int wm = w & 3, wn = w >> 2;
    const int g = l >> 2, tg = l & 3;
    const int m0 = blockIdx.x * 128, n0 = blockIdx.y * 128;

    // load B tile [128 x 96] -> smem rows of 104
    {
        const uint4* Bg = (const uint4*)(g_Bbf + (size_t)n0 * KD);
        uint4* Bs4 = (uint4*)Bs;
        for (int i = tid; i < 128 * 12; i += 256) {
            int r = i / 12, u = i - r * 12;
            Bs4[r * 13 + u] = Bg[r * 12 + u];
        }
        if (tid < 128) s_bias[tid] = bho[n0 + tid];
    }
    __syncthreads();

    // per-thread B ldmatrix base (row = n within tile, col half by lane group)
    const uint32_t bB = smem_u32(Bs) + (uint32_t)(((wn * 64 + (l & 7)) * 104 + ((l >> 3) & 1) * 8) * 2);
    // per-thread A base in global
    const __nv_bfloat16* pA = g_Abf + (size_t)(m0 + wm * 32 + g) * KD + 2 * tg;

    float c[2][8][4];
#pragma unroll
    for (int mt = 0; mt < 2; mt++)
#pragma unroll
        for (int nt = 0; nt < 8; nt++)
#pragma unroll
            for (int j = 0; j < 4; j++) c[mt][nt][j] = 0.f;

#pragma unroll
    for (int kt = 0; kt < 6; kt++) {
        uint32_t a[2][4];
#pragma unroll
        for (int mt = 0; mt < 2; mt++) {
            const __nv_bfloat16* p = pA + mt * 16 * KD + kt * 16;
            a[mt][0] = *(const uint32_t*)(p);
            a[mt][1] = *(const uint32_t*)(p + 8 * KD);
            a[mt][2] = *(const uint32_t*)(p + 8);
            a[mt][3] = *(const uint32_t*)(p + 8 * KD + 8);
        }
#pragma unroll
        for (int nt = 0; nt < 8; nt++) {
            uint32_t b0, b1;
            ldsm_x2(b0, b1, bB + (uint32_t)((nt * 8 * 104 + kt * 16) * 2));
            mma16816(c[0][nt], a[0], b0, b1);
            mma16816(c[1][nt], a[1], b0, b1);
        }
    }

    if (PASS == 1) {
        float sums[2][2] = {{0.f, 0.f}, {0.f, 0.f}};
#pragma unroll
        for (int mt = 0; mt < 2; mt++)
#pragma unroll
            for (int nt = 0; nt < 8; nt++) {
                int cb = wn * 64 + nt * 8 + 2 * tg;
                float b0v = s_bias[cb], b1v = s_bias[cb + 1];
                sums[mt][0] += __expf(c[mt][nt][0] + b0v - 16.f) + __expf(c[mt][nt][1] + b1v - 16.f);
                sums[mt][1] += __expf(c[mt][nt][2] + b0v - 16.f) + __expf(c[mt][nt][3] + b1v - 16.f);
            }
#pragma unroll
        for (int mt = 0; mt < 2; mt++)
#pragma unroll
            for (int hf = 0; hf < 2; hf++) {
                float v = sums[mt][hf];
                v += __shfl_xor_sync(0xffffffffu, v, 1);
                v += __shfl_xor_sync(0xffffffffu, v, 2);
                if (tg == 0) s_red[w * 32 + mt * 16 + hf * 8 + g] = v;
            }
        __syncthreads();
        if (tid < 128)
            g_part[(size_t)blockIdx.y * MT + m0 + tid] = s_red[tid] + s_red[128 + tid];
    } else {
        float lse[2][2];
        const int rbase = m0 + wm * 32 + g;
#pragma unroll
        for (int mt = 0; mt < 2; mt++) {
            lse[mt][0] = g_lse[rbase + mt * 16];
            lse[mt][1] = g_lse[rbase + mt * 16 + 8];
        }
#pragma unroll
        for (int mt = 0; mt < 2; mt++) {
            float* r0 = out + (size_t)(rbase + mt * 16) * V + n0 + wn * 64 + 2 * tg;
            float* r1 = r0 + 8 * V;
#pragma unroll
            for (int nt = 0; nt < 8; nt++) {
                int cb = wn * 64 + nt * 8 + 2 * tg;
                float b0v = s_bias[cb], b1v = s_bias[cb + 1];
                stcs2(r0 + nt * 8, c[mt][nt][0] + b0v - lse[mt][0], c[mt][nt][1] + b1v - lse[mt][0]);
                stcs2(r1 + nt * 8, c[mt][nt][2] + b0v - lse[mt][1], c[mt][nt][3] + b1v - lse[mt][1]);
            }
        }
    }
}

__global__ void lse_kernel() {
    int i = blockIdx.x * blockDim.x + threadIdx.x;
    if (i >= MT) return;
    float s = 0.f;
    for (int c = 0; c < NB; c++) s += g_part[(size_t)c * MT + i];
    g_lse[i] = 16.f + logf(s);
}

// ---------------------------------------------------------------------------
extern "C" void kernel_launch(void* const* d_in, const int* in_sizes, int n_in,
                              void* d_out, int out_size) {
    const int*   tok     = (const int*)  d_in[0];
    const float* mask_lr = (const float*)d_in[1];
    const float* mask_rl = (const float*)d_in[2];
    const float* emb     = (const float*)d_in[3];
    const float* W_lr    = (const float*)d_in[4];
    const float* b_lr    = (const float*)d_in[5];
    const float* W_rl    = (const float*)d_in[6];
    const float* b_rl    = (const float*)d_in[7];
    const float* W_ho    = (const float*)d_in[8];
    const float* b_ho    = (const float*)d_in[9];
    const float* h0      = (const float*)d_in[10];
    float* out = (float*)d_out;

    xproj_kernel<<<512, 256>>>(tok, emb, W_lr, b_lr, W_rl, b_rl);
    rnn_kernel<<<16, 32>>>(mask_lr, mask_rl, W_lr, W_rl, h0);
    prepA_kernel<<<512, 256>>>();
    prepB_kernel<<<4000, 256>>>(W_ho);
    gemm_kernel<1><<<dim3(32, NB), 256>>>(b_ho, out);
    lse_kernel<<<16, 256>>>();
    gemm_kernel<2><<<dim3(32, NB), 256>>>(b_ho, out);
}

// round 4
// speedup vs baseline: 1.5475x; 1.1744x over previous
#include <cuda_runtime.h>
#include <cuda_bf16.h>
#include <cstdint>

#define V  32000
#define SQ 256
#define BQ 16
#define HQ 16
#define MT 4096            // rows = SQ*BQ
#define NB 250             // N blocks (32000/128)
#define KD 96              // split-K depth: [hi|hi|lo] x [hi|lo|hi]

// ---------------- scratch (__device__ globals; no allocs) -------------------
__device__ float g_xproj[2 * SQ * BQ * HQ];
__device__ float g_hcat[MT * 32];
__device__ __nv_bfloat16 g_Abf[MT * KD];
__device__ __nv_bfloat16 g_Bbf[(size_t)V * KD];
__device__ float g_part[(size_t)NB * MT];
__device__ float g_lse[MT];

__device__ __forceinline__ uint32_t smem_u32(const void* p) {
    uint32_t a;
    asm("{ .reg .u64 t; cvta.to.shared.u64 t, %1; cvt.u32.u64 %0, t; }" : "=r"(a) : "l"(p));
    return a;
}
__device__ __forceinline__ void ldsm_x4(uint32_t* r, uint32_t addr) {
    asm volatile("ldmatrix.sync.aligned.m8n8.x4.shared.b16 {%0,%1,%2,%3}, [%4];"
                 : "=r"(r[0]), "=r"(r[1]), "=r"(r[2]), "=r"(r[3]) : "r"(addr));
}
__device__ __forceinline__ void mma16816(float* c, const uint32_t* a, uint32_t b0, uint32_t b1) {
    asm volatile("mma.sync.aligned.m16n8k16.row.col.f32.bf16.bf16.f32 "
                 "{%0,%1,%2,%3}, {%4,%5,%6,%7}, {%8,%9}, {%0,%1,%2,%3};"
                 : "+f"(c[0]), "+f"(c[1]), "+f"(c[2]), "+f"(c[3])
                 : "r"(a[0]), "r"(a[1]), "r"(a[2]), "r"(a[3]), "r"(b0), "r"(b1));
}
__device__ __forceinline__ void stcs2(float* p, float x, float y) {
    asm volatile("st.global.cs.v2.f32 [%0], {%1,%2};" :: "l"(p), "f"(x), "f"(y) : "memory");
}

// ---------------------------------------------------------------------------
__global__ void xproj_kernel(const int* __restrict__ tok, const float* __restrict__ emb,
                             const float* __restrict__ W_lr, const float* __restrict__ b_lr,
                             const float* __restrict__ W_rl, const float* __restrict__ b_rl) {
    int idx = blockIdx.x * blockDim.x + threadIdx.x;
    if (idx >= 2 * SQ * BQ * HQ) return;
    int h = idx & 15, b = (idx >> 4) & 15, s = (idx >> 8) & 255, dir = idx >> 16;
    const float* W = dir ? W_rl : W_lr;
    const float* bb = dir ? b_rl : b_lr;
    int t = tok[s * BQ + b];
    float acc = bb[h];
    const float* erow = emb + (size_t)t * 32;
#pragma unroll
    for (int e = 0; e < 32; e++) acc = fmaf(erow[e], W[e * HQ + h], acc);
    g_xproj[idx] = acc;
}

__global__ void rnn_kernel(const float* __restrict__ mask_lr, const float* __restrict__ mask_rl,
                           const float* __restrict__ W_lr, const float* __restrict__ W_rl,
                           const float* __restrict__ h0p) {
    const int b = blockIdx.x, lane = threadIdx.x;
    const bool rl = lane >= 16;
    const int h = lane & 15;
    const unsigned grpbase = lane & 16;
    const float* W = rl ? W_rl : W_lr;
    const float* mask = rl ? mask_rl : mask_lr;
    const float* xp = g_xproj + (rl ? SQ * BQ * HQ : 0);
    float Wh[16];
#pragma unroll
    for (int j = 0; j < 16; j++) Wh[j] = W[(32 + j) * HQ + h];
    float hv = h0p[h];
    if (!rl) g_hcat[(0 * BQ + b) * 32 + h] = hv;
    else     g_hcat[((SQ - 1) * BQ + b) * 32 + 16 + h] = hv;
    for (int t = 0; t < SQ; t++) {
        int s = rl ? (SQ - 1 - t) : t;
        float acc0 = xp[(s * BQ + b) * HQ + h];
        float acc1 = 0.f;
        float m = mask[(s * BQ + b) * HQ + h];
#pragma unroll
        for (int j = 0; j < 8; j++) {
            float hj0 = __shfl_sync(0xffffffffu, hv, grpbase + j);
            float hj1 = __shfl_sync(0xffffffffu, hv, grpbase + 8 + j);
            acc0 = fmaf(Wh[j], hj0, acc0);
            acc1 = fmaf(Wh[8 + j], hj1, acc1);
        }
        hv = tanhf(acc0 + acc1) * (m * (1.0f / 0.6f));
        if (!rl) { if (s < SQ - 1) g_hcat[((s + 1) * BQ + b) * 32 + h] = hv; }
        else     { if (s > 0)      g_hcat[((s - 1) * BQ + b) * 32 + 16 + h] = hv; }
    }
}

// A row m: [hi(32) | hi(32) | lo(32)]
__global__ void prepA_kernel() {
    int idx = blockIdx.x * blockDim.x + threadIdx.x;
    if (idx >= MT * 32) return;
    int m = idx >> 5, f = idx & 31;
    float a = g_hcat[m * 32 + f];
    __nv_bfloat16 hi = __float2bfloat16(a);
    __nv_bfloat16 lo = __float2bfloat16(a - __bfloat162float(hi));
    __nv_bfloat16* r = g_Abf + m * KD;
    r[f] = hi; r[32 + f] = hi; r[64 + f] = lo;
}

// B row n: [hi(32) | lo(32) | hi(32)],  w[k] = W_ho[k][n]
__global__ void prepB_kernel(const float* __restrict__ Who) {
    int idx = blockIdx.x * blockDim.x + threadIdx.x;
    if (idx >= V * 32) return;
    int n = idx >> 5, k = idx & 31;
    float w = Who[k * V + n];
    __nv_bfloat16 hi = __float2bfloat16(w);
    __nv_bfloat16 lo = __float2bfloat16(w - __bfloat162float(hi));
    __nv_bfloat16* r = g_Bbf + (size_t)n * KD;
    r[k] = hi; r[32 + k] = lo; r[64 + k] = hi;
}

// ---------------------------------------------------------------------------
// GEMM via mma.sync m16n8k16 bf16. CTA 128x128, warps 4(M) x 2(N), warp 32x64.
// A and B both staged in smem (padded stride 104 = 13x16B, ldmatrix conflict-free).
// PASS 1: lse partials. PASS 2: normalize + streaming store.
// ---------------------------------------------------------------------------
static constexpr int TSTR = 104;                       // bf16 row stride in smem
static constexpr int SM_AS = 0;                        // 128*104*2 = 26624
static constexpr int SM_BS = 26624;                    // 26624
static constexpr int SM_BIAS = 53248;                  // 512
static constexpr int SM_RED = 53760;                   // 1024
static constexpr int SMEM_BYTES = 54784;

template <int PASS>
__global__ void __launch_bounds__(256, 2)
gemm_kernel(const float* __restrict__ bho, float* __restrict__ out) {
    extern __shared__ char smem[];
    __nv_bfloat16* As = (__nv_bfloat16*)(smem + SM_AS);
    __nv_bfloat16* Bs = (__nv_bfloat16*)(smem + SM_BS);
    float* s_bias = (float*)(smem + SM_BIAS);
    float* s_red  = (float*)(smem + SM_RED);

    const int tid = threadIdx.x, w = tid >> 5, l = tid & 31;
    const int wm = w & 3, wn = w >> 2;
    const int g = l >> 2, tg = l & 3;
    const int m0 = blockIdx.x * 128, n0 = blockIdx.y * 128;

    // load A tile [128 x 96] and B tile [128 x 96] -> smem rows of 104
    {
        const uint4* Ag = (const uint4*)(g_Abf + (size_t)m0 * KD);
        const uint4* Bg = (const uint4*)(g_Bbf + (size_t)n0 * KD);
        uint4* As4 = (uint4*)As;
        uint4* Bs4 = (uint4*)Bs;
        for (int i = tid; i < 128 * 12; i += 256) {
            int r = i / 12, u = i - r * 12;
            As4[r * 13 + u] = Ag[r * 12 + u];
            Bs4[r * 13 + u] = Bg[r * 12 + u];
        }
        if (tid < 128) s_bias[tid] = bho[n0 + tid];
    }
    __syncthreads();

    const uint32_t aB = smem_u32(As);
    const uint32_t bB = smem_u32(Bs);
    // ldmatrix lane addressing
    const int j = l >> 3, r8 = l & 7;
    // A x4: row = wm*32 + mt*16 + (j&1)*8 + r8, col = kt*16 + (j>>1)*8
    const uint32_t aRow = (uint32_t)(wm * 32 + (j & 1) * 8 + r8);
    const uint32_t aColJ = (uint32_t)((j >> 1) * 8);
    // B x4 (nt pair p): row = wn*64 + p*16 + (j>>1)*8 + r8, col = kt*16 + (j&1)*8
    const uint32_t bRow = (uint32_t)(wn * 64 + (j >> 1) * 8 + r8);
    const uint32_t bColJ = (uint32_t)((j & 1) * 8);

    float c[2][8][4];
#pragma unroll
    for (int mt = 0; mt < 2; mt++)
#pragma unroll
        for (int nt = 0; nt < 8; nt++)
#pragma unroll
            for (int q = 0; q < 4; q++) c[mt][nt][q] = 0.f;

#pragma unroll
    for (int kt = 0; kt < 6; kt++) {
        uint32_t a[2][4];
#pragma unroll
        for (int mt = 0; mt < 2; mt++)
            ldsm_x4(a[mt], aB + 2u * ((aRow + mt * 16) * TSTR + kt * 16 + aColJ));
#pragma unroll
        for (int p = 0; p < 4; p++) {
            uint32_t b[4];
            ldsm_x4(b, bB + 2u * ((bRow + p * 16) * TSTR + kt * 16 + bColJ));
            mma16816(c[0][2 * p],     a[0], b[0], b[1]);
            mma16816(c[1][2 * p],     a[1], b[0], b[1]);
            mma16816(c[0][2 * p + 1], a[0], b[2], b[3]);
            mma16816(c[1][2 * p + 1], a[1], b[2], b[3]);
        }
    }

    if (PASS == 1) {
        float sums[2][2] = {{0.f, 0.f}, {0.f, 0.f}};
#pragma unroll
        for (int mt = 0; mt < 2; mt++)
#pragma unroll
            for (int nt = 0; nt < 8; nt++) {
                int cb = wn * 64 + nt * 8 + 2 * tg;
                float b0v = s_bias[cb], b1v = s_bias[cb + 1];
                sums[mt][0] += __expf(c[mt][nt][0] + b0v - 16.f) + __expf(c[mt][nt][1] + b1v - 16.f);
                sums[mt][1] += __expf(c[mt][nt][2] + b0v - 16.f) + __expf(c[mt][nt][3] + b1v - 16.f);
            }
#pragma unroll
        for (int mt = 0; mt < 2; mt++)
#pragma unroll
            for (int hf = 0; hf < 2; hf++) {
                float v = sums[mt][hf];
                v += __shfl_xor_sync(0xffffffffu, v, 1);
                v += __shfl_xor_sync(0xffffffffu, v, 2);
                if (tg == 0) s_red[w * 32 + mt * 16 + hf * 8 + g] = v;
            }
        __syncthreads();
        if (tid < 128)
            g_part[(size_t)blockIdx.y * MT + m0 + tid] = s_red[tid] + s_red[128 + tid];
    } else {
        float lse[2][2];
        const int rbase = m0 + wm * 32 + g;
#pragma unroll
        for (int mt = 0; mt < 2; mt++) {
            lse[mt][0] = g_lse[rbase + mt * 16];
            lse[mt][1] = g_lse[rbase + mt * 16 + 8];
        }
#pragma unroll
        for (int mt = 0; mt < 2; mt++) {
            float* r0 = out + (size_t)(rbase + mt * 16) * V + n0 + wn * 64 + 2 * tg;
            float* r1 = r0 + 8 * V;
#pragma unroll
            for (int nt = 0; nt < 8; nt++) {
                int cb = wn * 64 + nt * 8 + 2 * tg;
                float b0v = s_bias[cb], b1v = s_bias[cb + 1];
                stcs2(r0 + nt * 8, c[mt][nt][0] + b0v - lse[mt][0], c[mt][nt][1] + b1v - lse[mt][0]);
                stcs2(r1 + nt * 8, c[mt][nt][2] + b0v - lse[mt][1], c[mt][nt][3] + b1v - lse[mt][1]);
            }
        }
    }
}

__global__ void lse_kernel() {
    int i = blockIdx.x * blockDim.x + threadIdx.x;
    if (i >= MT) return;
    float s = 0.f;
    for (int c = 0; c < NB; c++) s += g_part[(size_t)c * MT + i];
    g_lse[i] = 16.f + logf(s);
}

// ---------------------------------------------------------------------------
extern "C" void kernel_launch(void* const* d_in, const int* in_sizes, int n_in,
                              void* d_out, int out_size) {
    const int*   tok     = (const int*)  d_in[0];
    const float* mask_lr = (const float*)d_in[1];
    const float* mask_rl = (const float*)d_in[2];
    const float* emb     = (const float*)d_in[3];
    const float* W_lr    = (const float*)d_in[4];
    const float* b_lr    = (const float*)d_in[5];
    const float* W_rl    = (const float*)d_in[6];
    const float* b_rl    = (const float*)d_in[7];
    const float* W_ho    = (const float*)d_in[8];
    const float* b_ho    = (const float*)d_in[9];
    const float* h0      = (const float*)d_in[10];
    float* out = (float*)d_out;

    cudaFuncSetAttribute(gemm_kernel<1>, cudaFuncAttributeMaxDynamicSharedMemorySize, SMEM_BYTES);
    cudaFuncSetAttribute(gemm_kernel<2>, cudaFuncAttributeMaxDynamicSharedMemorySize, SMEM_BYTES);

    xproj_kernel<<<512, 256>>>(tok, emb, W_lr, b_lr, W_rl, b_rl);
    rnn_kernel<<<16, 32>>>(mask_lr, mask_rl, W_lr, W_rl, h0);
    prepA_kernel<<<512, 256>>>();
    prepB_kernel<<<4000, 256>>>(W_ho);
    gemm_kernel<1><<<dim3(32, NB), 256, SMEM_BYTES>>>(b_ho, out);
    lse_kernel<<<16, 256>>>();
    gemm_kernel<2><<<dim3(32, NB), 256, SMEM_BYTES>>>(b_ho, out);
}

// round 7
// speedup vs baseline: 2.4584x; 1.5886x over previous
#include <cuda_runtime.h>
#include <cuda_fp16.h>
#include <cstdint>

#define V  32000
#define SQ 256
#define BQ 16
#define HQ 16
#define MT 4096            // rows = SQ*BQ
#define NB 250             // N blocks (32000/128)
#define KD 32              // fp16 direct K

// ---------------- scratch (__device__ globals; no allocs) -------------------
__device__ float g_xproj[2 * SQ * BQ * HQ];
__device__ float g_hcat[MT * 32];
__device__ __half g_Ah[MT * KD];
__device__ __half g_Bh[(size_t)V * KD];
__device__ float g_part[(size_t)NB * MT];
__device__ float g_lse[MT];

__device__ __forceinline__ uint32_t smem_u32(const void* p) {
    uint32_t a;
    asm("{ .reg .u64 t; cvta.to.shared.u64 t, %1; cvt.u32.u64 %0, t; }" : "=r"(a) : "l"(p));
    return a;
}
__device__ __forceinline__ void ldsm_x4(uint32_t* r, uint32_t addr) {
    asm volatile("ldmatrix.sync.aligned.m8n8.x4.shared.b16 {%0,%1,%2,%3}, [%4];"
                 : "=r"(r[0]), "=r"(r[1]), "=r"(r[2]), "=r"(r[3]) : "r"(addr));
}
__device__ __forceinline__ void mma16816(float* c, const uint32_t* a, uint32_t b0, uint32_t b1) {
    asm volatile("mma.sync.aligned.m16n8k16.row.col.f32.f16.f16.f32 "
                 "{%0,%1,%2,%3}, {%4,%5,%6,%7}, {%8,%9}, {%0,%1,%2,%3};"
                 : "+f"(c[0]), "+f"(c[1]), "+f"(c[2]), "+f"(c[3])
                 : "r"(a[0]), "r"(a[1]), "r"(a[2]), "r"(a[3]), "r"(b0), "r"(b1));
}
__device__ __forceinline__ void stcs2(float* p, float x, float y) {
    asm volatile("st.global.cs.v2.f32 [%0], {%1,%2};" :: "l"(p), "f"(x), "f"(y) : "memory");
}

// ---------------------------------------------------------------------------
__global__ void xproj_kernel(const int* __restrict__ tok, const float* __restrict__ emb,
                             const float* __restrict__ W_lr, const float* __restrict__ b_lr,
                             const float* __restrict__ W_rl, const float* __restrict__ b_rl) {
    int idx = blockIdx.x * blockDim.x + threadIdx.x;
    if (idx >= 2 * SQ * BQ * HQ) return;
    int h = idx & 15, b = (idx >> 4) & 15, s = (idx >> 8) & 255, dir = idx >> 16;
    const float* W = dir ? W_rl : W_lr;
    const float* bb = dir ? b_rl : b_lr;
    int t = tok[s * BQ + b];
    float acc = bb[h];
    const float* erow = emb + (size_t)t * 32;
#pragma unroll
    for (int e = 0; e < 32; e++) acc = fmaf(erow[e], W[e * HQ + h], acc);
    g_xproj[idx] = acc;
}

__global__ void rnn_kernel(const float* __restrict__ mask_lr, const float* __restrict__ mask_rl,
                           const float* __restrict__ W_lr, const float* __restrict__ W_rl,
                           const float* __restrict__ h0p) {
    const int b = blockIdx.x, lane = threadIdx.x;
    const bool rl = lane >= 16;
    const int h = lane & 15;
    const unsigned grpbase = lane & 16;
    const float* W = rl ? W_rl : W_lr;
    const float* mask = rl ? mask_rl : mask_lr;
    const float* xp = g_xproj + (rl ? SQ * BQ * HQ : 0);
    float Wh[16];
#pragma unroll
    for (int j = 0; j < 16; j++) Wh[j] = W[(32 + j) * HQ + h];
    float hv = h0p[h];
    if (!rl) g_hcat[(0 * BQ + b) * 32 + h] = hv;
    else     g_hcat[((SQ - 1) * BQ + b) * 32 + 16 + h] = hv;

    int s0 = rl ? (SQ - 1) : 0;
    float xv = xp[(s0 * BQ + b) * HQ + h];
    float mv = mask[(s0 * BQ + b) * HQ + h];
    for (int t = 0; t < SQ; t++) {
        int s = rl ? (SQ - 1 - t) : t;
        float xn = 0.f, mn = 0.f;
        if (t < SQ - 1) {
            int sn = rl ? (s - 1) : (s + 1);
            xn = xp[(sn * BQ + b) * HQ + h];
            mn = mask[(sn * BQ + b) * HQ + h];
        }
        float acc0 = xv, acc1 = 0.f;
#pragma unroll
        for (int j = 0; j < 8; j++) {
            float hj0 = __shfl_sync(0xffffffffu, hv, grpbase + j);
            float hj1 = __shfl_sync(0xffffffffu, hv, grpbase + 8 + j);
            acc0 = fmaf(Wh[j], hj0, acc0);
            acc1 = fmaf(Wh[8 + j], hj1, acc1);
        }
        hv = tanhf(acc0 + acc1) * (mv * (1.0f / 0.6f));
        if (!rl) { if (s < SQ - 1) g_hcat[((s + 1) * BQ + b) * 32 + h] = hv; }
        else     { if (s > 0)      g_hcat[((s - 1) * BQ + b) * 32 + 16 + h] = hv; }
        xv = xn; mv = mn;
    }
}

__global__ void prepA_kernel() {
    int idx = blockIdx.x * blockDim.x + threadIdx.x;
    if (idx >= MT * 32) return;
    int m = idx >> 5, f = idx & 31;
    g_Ah[m * KD + f] = __float2half_rn(g_hcat[m * 32 + f]);
}

// B row n: w[k] = W_ho[k][n]
__global__ void prepB_kernel(const float* __restrict__ Who) {
    int idx = blockIdx.x * blockDim.x + threadIdx.x;
    if (idx >= V * 32) return;
    int n = idx >> 5, k = idx & 31;
    g_Bh[(size_t)n * KD + k] = __float2half_rn(Who[k * V + n]);
}

// ---------------------------------------------------------------------------
// GEMM via mma.sync m16n8k16 fp16. CTA 128x128, warps 4(M) x 2(N), warp 32x64.
// Smem row stride 40 halfs (80B) -> ldmatrix conflict-free.
// PASS 1: lse partials. PASS 2: normalize + streaming store.
// ---------------------------------------------------------------------------
static constexpr int TSTR = 40;

template <int PASS>
__global__ void __launch_bounds__(256, 2)
gemm_kernel(const float* __restrict__ bho, float* __restrict__ out) {
    __shared__ __align__(16) __half As[128 * TSTR];
    __shared__ __align__(16) __half Bs[128 * TSTR];
    __shared__ float s_bias[128];
    __shared__ float s_red[256];

    const int tid = threadIdx.x, w = tid >> 5, l = tid & 31;
    const int wm = w & 3, wn = w >> 2;
    const int g = l >> 2, tg = l & 3;
    const int m0 = blockIdx.x * 128, n0 = blockIdx.y * 128;

    // load A and B tiles [128 x 32] -> smem rows of 40 halfs (5 uint4)
    {
        const uint4* Ag = (const uint4*)(g_Ah + (size_t)m0 * KD);
        const uint4* Bg = (const uint4*)(g_Bh + (size_t)n0 * KD);
        uint4* As4 = (uint4*)As;
        uint4* Bs4 = (uint4*)Bs;
#pragma unroll
        for (int i = tid; i < 512; i += 256) {       // 128 rows x 4 uint4
            int r = i >> 2, u = i & 3;
            As4[r * 5 + u] = Ag[r * 4 + u];
            Bs4[r * 5 + u] = Bg[r * 4 + u];
        }
        if (tid < 128) s_bias[tid] = bho[n0 + tid];
    }
    __syncthreads();

    const uint32_t aB = smem_u32(As);
    const uint32_t bB = smem_u32(Bs);
    const int j = l >> 3, r8 = l & 7;
    const uint32_t aRow = (uint32_t)(wm * 32 + (j & 1) * 8 + r8);
    const uint32_t aColJ = (uint32_t)((j >> 1) * 8);
    const uint32_t bRow = (uint32_t)(wn * 64 + (j >> 1) * 8 + r8);
    const uint32_t bColJ = (uint32_t)((j & 1) * 8);

    float c[2][8][4];
#pragma unroll
    for (int mt = 0; mt < 2; mt++)
#pragma unroll
        for (int nt = 0; nt < 8; nt++)
#pragma unroll
            for (int q = 0; q < 4; q++) c[mt][nt][q] = 0.f;

#pragma unroll
    for (int kt = 0; kt < 2; kt++) {
        uint32_t a[2][4];
#pragma unroll
        for (int mt = 0; mt < 2; mt++)
            ldsm_x4(a[mt], aB + 2u * ((aRow + mt * 16) * TSTR + kt * 16 + aColJ));
#pragma unroll
        for (int p = 0; p < 4; p++) {
            uint32_t b[4];
            ldsm_x4(b, bB + 2u * ((bRow + p * 16) * TSTR + kt * 16 + bColJ));
            mma16816(c[0][2 * p],     a[0], b[0], b[1]);
            mma16816(c[1][2 * p],     a[1], b[0], b[1]);
            mma16816(c[0][2 * p + 1], a[0], b[2], b[3]);
            mma16816(c[1][2 * p + 1], a[1], b[2], b[3]);
        }
    }

    if (PASS == 1) {
        float sums[2][2] = {{0.f, 0.f}, {0.f, 0.f}};
#pragma unroll
        for (int mt = 0; mt < 2; mt++)
#pragma unroll
            for (int nt = 0; nt < 8; nt++) {
                int cb = wn * 64 + nt * 8 + 2 * tg;
                float b0v = s_bias[cb], b1v = s_bias[cb + 1];
                sums[mt][0] += __expf(c[mt][nt][0] + b0v - 16.f) + __expf(c[mt][nt][1] + b1v - 16.f);
                sums[mt][1] += __expf(c[mt][nt][2] + b0v - 16.f) + __expf(c[mt][nt][3] + b1v - 16.f);
            }
#pragma unroll
        for (int mt = 0; mt < 2; mt++)
#pragma unroll
            for (int hf = 0; hf < 2; hf++) {
                float v = sums[mt][hf];
                v += __shfl_xor_sync(0xffffffffu, v, 1);
                v += __shfl_xor_sync(0xffffffffu, v, 2);
                if (tg == 0) s_red[w * 32 + mt * 16 + hf * 8 + g] = v;
            }
        __syncthreads();
        if (tid < 128)
            g_part[(size_t)blockIdx.y * MT + m0 + tid] = s_red[tid] + s_red[128 + tid];
    } else {
        float lse[2][2];
        const int rbase = m0 + wm * 32 + g;
#pragma unroll
        for (int mt = 0; mt < 2; mt++) {
            lse[mt][0] = g_lse[rbase + mt * 16];
            lse[mt][1] = g_lse[rbase + mt * 16 + 8];
        }
#pragma unroll
        for (int mt = 0; mt < 2; mt++) {
            float* r0 = out + (size_t)(rbase + mt * 16) * V + n0 + wn * 64 + 2 * tg;
            float* r1 = r0 + 8 * V;
#pragma unroll
            for (int nt = 0; nt < 8; nt++) {
                int cb = wn * 64 + nt * 8 + 2 * tg;
                float b0v = s_bias[cb], b1v = s_bias[cb + 1];
                stcs2(r0 + nt * 8, c[mt][nt][0] + b0v - lse[mt][0], c[mt][nt][1] + b1v - lse[mt][0]);
                stcs2(r1 + nt * 8, c[mt][nt][2] + b0v - lse[mt][1], c[mt][nt][3] + b1v - lse[mt][1]);
            }
        }
    }
}

__global__ void lse_kernel() {
    int i = blockIdx.x * blockDim.x + threadIdx.x;
    if (i >= MT) return;
    float s = 0.f;
    for (int c = 0; c < NB; c++) s += g_part[(size_t)c * MT + i];
    g_lse[i] = 16.f + logf(s);
}

// ---------------------------------------------------------------------------
extern "C" void kernel_launch(void* const* d_in, const int* in_sizes, int n_in,
                              void* d_out, int out_size) {
    const int*   tok     = (const int*)  d_in[0];
    const float* mask_lr = (const float*)d_in[1];
    const float* mask_rl = (const float*)d_in[2];
    const float* emb     = (const float*)d_in[3];
    const float* W_lr    = (const float*)d_in[4];
    const float* b_lr    = (const float*)d_in[5];
    const float* W_rl    = (const float*)d_in[6];
    const float* b_rl    = (const float*)d_in[7];
    const float* W_ho    = (const float*)d_in[8];
    const float* b_ho    = (const float*)d_in[9];
    const float* h0      = (const float*)d_in[10];
    float* out = (float*)d_out;

    xproj_kernel<<<512, 256>>>(tok, emb, W_lr, b_lr, W_rl, b_rl);
    rnn_kernel<<<16, 32>>>(mask_lr, mask_rl, W_lr, W_rl, h0);
    prepA_kernel<<<512, 256>>>();
    prepB_kernel<<<4000, 256>>>(W_ho);
    gemm_kernel<1><<<dim3(32, NB), 256>>>(b_ho, out);
    lse_kernel<<<16, 256>>>();
    gemm_kernel<2><<<dim3(32, NB), 256>>>(b_ho, out);
}